// round 1
// baseline (speedup 1.0000x reference)
#include <cuda_runtime.h>
#include <cuda_bf16.h>
#include <float.h>

#define T_SEQ 2048
#define H_HEADS 16
#define D_QK 192      // NOPE + ROPE
#define D_NOPE 128
#define D_ROPE 64
#define D_V 128
#define L_LORA 512
#define SCALE_F 0.07216878364870323f   // 1/sqrt(192)

// Scratch (allocation-free rule: device globals)
__device__ float g_K[H_HEADS * T_SEQ * D_QK];   // [h][t][192]
__device__ float g_V[H_HEADS * T_SEQ * D_V];    // [h][t][128]

// ---------------------------------------------------------------------------
// Prep GEMM: z=0 -> K_nope = k_c @ w_kv_b (per-head 128-col slices)
//            z=1 -> V[h]   = k_c @ w_uv[h]
// C tile 64x64, K-chunk 16, 256 threads, 4x4 per thread.
// ---------------------------------------------------------------------------
__global__ __launch_bounds__(256) void prep_gemm(
    const float* __restrict__ kc,     // [T, 512]
    const float* __restrict__ wkvb,   // [512, 4096]
    const float* __restrict__ wuv)    // [16, 512, 128]
{
    __shared__ float As[64][16];
    __shared__ float Bs[16][64];

    const int t0 = blockIdx.x * 64;
    const int n0 = blockIdx.y * 64;       // column in the 2048-wide output
    const int z  = blockIdx.z;
    const int tid = threadIdx.x;
    const int tx = tid & 15;
    const int ty = tid >> 4;

    const int arow = tid >> 2;
    const int acol = (tid & 3) * 4;
    const int brow = tid >> 4;
    const int bcol = (tid & 15) * 4;

    // B source pointer pieces (head is constant within a 64-col tile)
    const int nb = n0 + bcol;
    const int hb = nb >> 7;
    const int db = nb & 127;

    float acc[4][4] = {};

    for (int l0 = 0; l0 < L_LORA; l0 += 16) {
        // load A (64x16)
        *(float4*)(&As[arow][acol]) =
            *(const float4*)(kc + (t0 + arow) * L_LORA + l0 + acol);
        // load B (16x64)
        const float* bsrc = (z == 0)
            ? (wkvb + (size_t)(l0 + brow) * 4096 + hb * 256 + db)
            : (wuv  + ((size_t)hb * 512 + (l0 + brow)) * 128 + db);
        *(float4*)(&Bs[brow][bcol]) = *(const float4*)bsrc;
        __syncthreads();

        #pragma unroll
        for (int kk = 0; kk < 16; kk++) {
            float ra[4];
            #pragma unroll
            for (int i = 0; i < 4; i++) ra[i] = As[ty * 4 + i][kk];
            float4 rb = *(const float4*)(&Bs[kk][tx * 4]);
            #pragma unroll
            for (int i = 0; i < 4; i++) {
                acc[i][0] += ra[i] * rb.x;
                acc[i][1] += ra[i] * rb.y;
                acc[i][2] += ra[i] * rb.z;
                acc[i][3] += ra[i] * rb.w;
            }
        }
        __syncthreads();
    }

    const int n = n0 + tx * 4;
    const int h = n >> 7;
    const int d = n & 127;
    #pragma unroll
    for (int i = 0; i < 4; i++) {
        const int t = t0 + ty * 4 + i;
        float4 o = make_float4(acc[i][0], acc[i][1], acc[i][2], acc[i][3]);
        if (z == 0)
            *(float4*)(g_K + ((size_t)h * T_SEQ + t) * D_QK + d) = o;
        else
            *(float4*)(g_V + ((size_t)h * T_SEQ + t) * D_V + d) = o;
    }
}

// ---------------------------------------------------------------------------
// ROPE fill: g_K[h][t][128+r] = k_pe[t][r]
// ---------------------------------------------------------------------------
__global__ __launch_bounds__(256) void rope_fill(const float* __restrict__ kpe)
{
    int idx = blockIdx.x * blockDim.x + threadIdx.x;
    if (idx >= H_HEADS * T_SEQ * D_ROPE) return;
    int r = idx & 63;
    int t = (idx >> 6) & (T_SEQ - 1);
    int h = idx >> 17;
    g_K[((size_t)h * T_SEQ + t) * D_QK + D_NOPE + r] = kpe[t * D_ROPE + r];
}

// ---------------------------------------------------------------------------
// Flash attention (fp32, causal), per head.
// Block = 32 query rows, 8 warps, 4 rows/warp; key tiles of 32.
// Shared strides: Qs 192, Ks 196, Vs 132 (float4-aligned, phase-conflict-free)
// ---------------------------------------------------------------------------
#define KS_STRIDE 196
#define VS_STRIDE 132
#define ATTN_SMEM ((32 * 192 + 32 * KS_STRIDE + 32 * VS_STRIDE) * 4)

__global__ __launch_bounds__(256) void attn_kernel(
    const float* __restrict__ q,    // [T, H, 192]
    float* __restrict__ out)        // [T, H*128]
{
    extern __shared__ float sm[];
    float* Qs = sm;                      // 32 * 192
    float* Ks = Qs + 32 * 192;           // 32 * 196
    float* Vs = Ks + 32 * KS_STRIDE;     // 32 * 132

    const int h  = blockIdx.y;
    const int t0 = blockIdx.x * 32;
    const int tid = threadIdx.x;
    const int warp = tid >> 5;
    const int lane = tid & 31;

    // load Q tile
    for (int idx = tid; idx < 32 * 192; idx += 256) {
        int r = idx / 192, d = idx - r * 192;
        Qs[r * 192 + d] = q[((size_t)(t0 + r) * H_HEADS + h) * D_QK + d];
    }

    float m[4], l[4];
    float4 acc[4];
    #pragma unroll
    for (int i = 0; i < 4; i++) {
        m[i] = -3.0e38f;
        l[i] = 0.0f;
        acc[i] = make_float4(0.f, 0.f, 0.f, 0.f);
    }

    const int ntiles = blockIdx.x + 1;      // keys 0 .. t0+31
    for (int tile = 0; tile < ntiles; tile++) {
        const int s0 = tile * 32;
        __syncthreads();
        for (int idx = tid; idx < 32 * 192; idx += 256) {
            int r = idx / 192, d = idx - r * 192;
            Ks[r * KS_STRIDE + d] = g_K[((size_t)h * T_SEQ + s0 + r) * D_QK + d];
        }
        for (int idx = tid; idx < 32 * 128; idx += 256) {
            int r = idx >> 7, d = idx & 127;
            Vs[r * VS_STRIDE + d] = g_V[((size_t)h * T_SEQ + s0 + r) * D_V + d];
        }
        __syncthreads();

        // scores: lane computes key column (s0+lane) for this warp's 4 rows
        const float4* kp = (const float4*)(Ks + lane * KS_STRIDE);
        float sc[4] = {0.f, 0.f, 0.f, 0.f};
        #pragma unroll 4
        for (int d4 = 0; d4 < 48; d4++) {
            float4 kv = kp[d4];
            #pragma unroll
            for (int i = 0; i < 4; i++) {
                float4 qv = ((const float4*)(Qs + (warp * 4 + i) * 192))[d4];
                sc[i] += kv.x * qv.x + kv.y * qv.y + kv.z * qv.z + kv.w * qv.w;
            }
        }

        const int s = s0 + lane;
        #pragma unroll
        for (int i = 0; i < 4; i++) {
            const int t = t0 + warp * 4 + i;
            float v = (s <= t) ? sc[i] * SCALE_F : -3.0e38f;
            // warp max
            float mx = v;
            #pragma unroll
            for (int off = 16; off; off >>= 1)
                mx = fmaxf(mx, __shfl_xor_sync(0xffffffffu, mx, off));
            const float mnew = fmaxf(m[i], mx);
            const float esc = __expf(m[i] - mnew);
            const float p = __expf(v - mnew);
            float psum = p;
            #pragma unroll
            for (int off = 16; off; off >>= 1)
                psum += __shfl_xor_sync(0xffffffffu, psum, off);
            l[i] = l[i] * esc + psum;
            m[i] = mnew;
            acc[i].x *= esc; acc[i].y *= esc; acc[i].z *= esc; acc[i].w *= esc;

            // P @ V for this row: lane owns output cols [lane*4, lane*4+4)
            #pragma unroll 8
            for (int jj = 0; jj < 32; jj++) {
                const float pj = __shfl_sync(0xffffffffu, p, jj);
                const float4 vv = *(const float4*)(Vs + jj * VS_STRIDE + lane * 4);
                acc[i].x += pj * vv.x;
                acc[i].y += pj * vv.y;
                acc[i].z += pj * vv.z;
                acc[i].w += pj * vv.w;
            }
        }
    }

    #pragma unroll
    for (int i = 0; i < 4; i++) {
        const int t = t0 + warp * 4 + i;
        const float inv = 1.0f / l[i];
        float4 o = make_float4(acc[i].x * inv, acc[i].y * inv,
                               acc[i].z * inv, acc[i].w * inv);
        *(float4*)(out + (size_t)t * (H_HEADS * D_V) + h * D_V + lane * 4) = o;
    }
}

// ---------------------------------------------------------------------------
extern "C" void kernel_launch(void* const* d_in, const int* in_sizes, int n_in,
                              void* d_out, int out_size)
{
    const float* q    = (const float*)d_in[0];   // (T, H, 192)
    const float* kc   = (const float*)d_in[1];   // (T, 512)
    const float* kpe  = (const float*)d_in[2];   // (T, 64)
    const float* wkvb = (const float*)d_in[3];   // (512, 4096)
    const float* wuv  = (const float*)d_in[4];   // (16, 512, 128)
    float* out = (float*)d_out;                  // (T, 2048)

    cudaFuncSetAttribute(attn_kernel,
                         cudaFuncAttributeMaxDynamicSharedMemorySize, ATTN_SMEM);

    prep_gemm<<<dim3(T_SEQ / 64, 2048 / 64, 2), 256>>>(kc, wkvb, wuv);
    rope_fill<<<(H_HEADS * T_SEQ * D_ROPE + 255) / 256, 256>>>(kpe);
    attn_kernel<<<dim3(T_SEQ / 32, H_HEADS), 256, ATTN_SMEM>>>(q, out);
}

// round 2
// speedup vs baseline: 5.0671x; 5.0671x over previous
#include <cuda_runtime.h>
#include <cuda_fp16.h>
#include <stdint.h>

#define T_SEQ 2048
#define H_HEADS 16
#define D_QK 192      // NOPE + ROPE
#define D_NOPE 128
#define D_ROPE 64
#define D_V 128
#define L_LORA 512
#define SCALE_F 0.07216878364870323f   // 1/sqrt(192)

// fp16 staging (device globals: allocation-free rule)
__device__ __half g_Qh[T_SEQ * H_HEADS * D_QK];   // [t][h][192], pre-scaled by SCALE
__device__ __half g_Kh[H_HEADS * T_SEQ * D_QK];   // [h][t][192]
__device__ __half g_Vh[H_HEADS * T_SEQ * D_V];    // [h][t][128]

// ---------------------------------------------------------------------------
// Prep GEMM (fp32 compute, fp16 output):
//   z=0 -> K_nope = k_c @ w_kv_b (per-head 128-col slices) -> g_Kh[..., 0:128]
//   z=1 -> V[h]   = k_c @ w_uv[h]                          -> g_Vh
// ---------------------------------------------------------------------------
__global__ __launch_bounds__(256) void prep_gemm(
    const float* __restrict__ kc,     // [T, 512]
    const float* __restrict__ wkvb,   // [512, 4096]
    const float* __restrict__ wuv)    // [16, 512, 128]
{
    __shared__ float As[64][16];
    __shared__ float Bs[16][64];

    const int t0 = blockIdx.x * 64;
    const int n0 = blockIdx.y * 64;
    const int z  = blockIdx.z;
    const int tid = threadIdx.x;
    const int tx = tid & 15;
    const int ty = tid >> 4;

    const int arow = tid >> 2;
    const int acol = (tid & 3) * 4;
    const int brow = tid >> 4;
    const int bcol = (tid & 15) * 4;

    const int nb = n0 + bcol;
    const int hb = nb >> 7;
    const int db = nb & 127;

    float acc[4][4] = {};

    for (int l0 = 0; l0 < L_LORA; l0 += 16) {
        *(float4*)(&As[arow][acol]) =
            *(const float4*)(kc + (t0 + arow) * L_LORA + l0 + acol);
        const float* bsrc = (z == 0)
            ? (wkvb + (size_t)(l0 + brow) * 4096 + hb * 256 + db)
            : (wuv  + ((size_t)hb * 512 + (l0 + brow)) * 128 + db);
        *(float4*)(&Bs[brow][bcol]) = *(const float4*)bsrc;
        __syncthreads();

        #pragma unroll
        for (int kk = 0; kk < 16; kk++) {
            float ra[4];
            #pragma unroll
            for (int i = 0; i < 4; i++) ra[i] = As[ty * 4 + i][kk];
            float4 rb = *(const float4*)(&Bs[kk][tx * 4]);
            #pragma unroll
            for (int i = 0; i < 4; i++) {
                acc[i][0] += ra[i] * rb.x;
                acc[i][1] += ra[i] * rb.y;
                acc[i][2] += ra[i] * rb.z;
                acc[i][3] += ra[i] * rb.w;
            }
        }
        __syncthreads();
    }

    const int n = n0 + tx * 4;
    const int h = n >> 7;
    const int d = n & 127;
    #pragma unroll
    for (int i = 0; i < 4; i++) {
        const int t = t0 + ty * 4 + i;
        __half2 h01 = __floats2half2_rn(acc[i][0], acc[i][1]);
        __half2 h23 = __floats2half2_rn(acc[i][2], acc[i][3]);
        __half* dst = (z == 0)
            ? (g_Kh + ((size_t)h * T_SEQ + t) * D_QK + d)
            : (g_Vh + ((size_t)h * T_SEQ + t) * D_V  + d);
        *(__half2*)(dst)     = h01;
        *(__half2*)(dst + 2) = h23;
    }
}

// ---------------------------------------------------------------------------
// ROPE fill (fp16): g_Kh[h][t][128+r] = k_pe[t][r]
// ---------------------------------------------------------------------------
__global__ __launch_bounds__(256) void rope_fill(const float* __restrict__ kpe)
{
    int idx = blockIdx.x * blockDim.x + threadIdx.x;
    if (idx >= H_HEADS * T_SEQ * D_ROPE) return;
    int r = idx & 63;
    int t = (idx >> 6) & (T_SEQ - 1);
    int h = idx >> 17;
    g_Kh[((size_t)h * T_SEQ + t) * D_QK + D_NOPE + r] = __float2half(kpe[t * D_ROPE + r]);
}

// ---------------------------------------------------------------------------
// Q convert + scale fold
// ---------------------------------------------------------------------------
__global__ __launch_bounds__(256) void q_convert(const float* __restrict__ q)
{
    int i = blockIdx.x * blockDim.x + threadIdx.x;        // float4 index
    const int n4 = (T_SEQ * H_HEADS * D_QK) / 4;
    if (i >= n4) return;
    float4 v = ((const float4*)q)[i];
    __half2 h0 = __floats2half2_rn(v.x * SCALE_F, v.y * SCALE_F);
    __half2 h1 = __floats2half2_rn(v.z * SCALE_F, v.w * SCALE_F);
    ((__half2*)g_Qh)[2 * i]     = h0;
    ((__half2*)g_Qh)[2 * i + 1] = h1;
}

// ---------------------------------------------------------------------------
// Flash attention, fp16 mma.sync.m16n8k16, fp32 accumulate, causal.
// Block = 64 q rows, 4 warps x 16 rows; key tiles of 64.
// SMEM strides padded so ldmatrix row addresses step 4 banks (conflict-free).
// ---------------------------------------------------------------------------
#define QS_STRIDE 200
#define KS_STRIDE 200
#define VS_STRIDE 136
#define ATTN_SMEM ((64 * QS_STRIDE + 64 * KS_STRIDE + 64 * VS_STRIDE) * 2)

__device__ __forceinline__ uint32_t sptr(const void* p) {
    return (uint32_t)__cvta_generic_to_shared(p);
}
__device__ __forceinline__ void ldm4(uint32_t& r0, uint32_t& r1, uint32_t& r2, uint32_t& r3, uint32_t addr) {
    asm volatile("ldmatrix.sync.aligned.m8n8.x4.shared.b16 {%0,%1,%2,%3}, [%4];"
                 : "=r"(r0), "=r"(r1), "=r"(r2), "=r"(r3) : "r"(addr));
}
__device__ __forceinline__ void ldm4t(uint32_t& r0, uint32_t& r1, uint32_t& r2, uint32_t& r3, uint32_t addr) {
    asm volatile("ldmatrix.sync.aligned.m8n8.x4.trans.shared.b16 {%0,%1,%2,%3}, [%4];"
                 : "=r"(r0), "=r"(r1), "=r"(r2), "=r"(r3) : "r"(addr));
}
__device__ __forceinline__ void mma16816(float* c,
                                         uint32_t a0, uint32_t a1, uint32_t a2, uint32_t a3,
                                         uint32_t b0, uint32_t b1) {
    asm volatile("mma.sync.aligned.m16n8k16.row.col.f32.f16.f16.f32 "
                 "{%0,%1,%2,%3}, {%4,%5,%6,%7}, {%8,%9}, {%0,%1,%2,%3};"
                 : "+f"(c[0]), "+f"(c[1]), "+f"(c[2]), "+f"(c[3])
                 : "r"(a0), "r"(a1), "r"(a2), "r"(a3), "r"(b0), "r"(b1));
}

__global__ __launch_bounds__(128, 3) void attn_kernel(float* __restrict__ out)
{
    extern __shared__ __half sm[];
    __half* Qs = sm;
    __half* Ks = Qs + 64 * QS_STRIDE;
    __half* Vs = Ks + 64 * KS_STRIDE;

    const int h  = blockIdx.y;
    const int t0 = blockIdx.x * 64;
    const int tid  = threadIdx.x;
    const int warp = tid >> 5;
    const int lane = tid & 31;

    // load Q tile (64 x 192 halfs = 64 x 24 uint4)
    for (int i = tid; i < 64 * 24; i += 128) {
        int r = i / 24, c = i - r * 24;
        *(uint4*)(Qs + r * QS_STRIDE + c * 8) =
            *(const uint4*)(g_Qh + ((size_t)(t0 + r) * H_HEADS + h) * D_QK + c * 8);
    }

    float m0 = -1e30f, m1 = -1e30f, l0 = 0.f, l1 = 0.f;
    float oacc[16][4];
    #pragma unroll
    for (int j = 0; j < 16; j++)
        #pragma unroll
        for (int e = 0; e < 4; e++) oacc[j][e] = 0.f;

    const int mrow = warp * 16;
    const int qr = lane >> 2;        // row within 8-group
    const int cq = (lane & 3) * 2;   // col pair base

    // ldmatrix base addresses (byte offsets added per step)
    const uint32_t qbase = sptr(Qs + (mrow + (lane & 15)) * QS_STRIDE + ((lane >> 4) << 3));
    const uint32_t kbase = sptr(Ks + ((lane & 7) + ((lane >> 4) << 3)) * KS_STRIDE + (((lane >> 3) & 1) << 3));
    const uint32_t vbase = sptr(Vs + (lane & 15) * VS_STRIDE + ((lane >> 4) << 3));

    const int ntiles = blockIdx.x + 1;
    for (int tile = 0; tile < ntiles; tile++) {
        const int s0 = tile * 64;
        __syncthreads();
        for (int i = tid; i < 64 * 24; i += 128) {
            int r = i / 24, c = i - r * 24;
            *(uint4*)(Ks + r * KS_STRIDE + c * 8) =
                *(const uint4*)(g_Kh + ((size_t)h * T_SEQ + s0 + r) * D_QK + c * 8);
        }
        for (int i = tid; i < 64 * 16; i += 128) {
            int r = i >> 4, c = i & 15;
            *(uint4*)(Vs + r * VS_STRIDE + c * 8) =
                *(const uint4*)(g_Vh + ((size_t)h * T_SEQ + s0 + r) * D_V + c * 8);
        }
        __syncthreads();

        // ---- scores S = Q @ K^T  (16 rows x 64 keys per warp) ----
        float sacc[8][4];
        #pragma unroll
        for (int j = 0; j < 8; j++)
            #pragma unroll
            for (int e = 0; e < 4; e++) sacc[j][e] = 0.f;

        #pragma unroll
        for (int kk = 0; kk < 12; kk++) {
            uint32_t a0, a1, a2, a3;
            ldm4(a0, a1, a2, a3, qbase + kk * 32);       // 16 halfs = 32 bytes
            #pragma unroll
            for (int j2 = 0; j2 < 4; j2++) {
                uint32_t b0, b1, b2, b3;
                ldm4(b0, b1, b2, b3, kbase + (uint32_t)(j2 * 16 * KS_STRIDE + kk * 16) * 2);
                mma16816(sacc[2 * j2],     a0, a1, a2, a3, b0, b1);
                mma16816(sacc[2 * j2 + 1], a0, a1, a2, a3, b2, b3);
            }
        }

        // ---- causal mask (only the diagonal tile) ----
        if (tile == blockIdx.x) {
            const int row0 = mrow + qr;   // relative, since s0 == t0
            #pragma unroll
            for (int j = 0; j < 8; j++) {
                int c0 = j * 8 + cq;
                if (c0     > row0)     sacc[j][0] = -1e30f;
                if (c0 + 1 > row0)     sacc[j][1] = -1e30f;
                if (c0     > row0 + 8) sacc[j][2] = -1e30f;
                if (c0 + 1 > row0 + 8) sacc[j][3] = -1e30f;
            }
        }

        // ---- online softmax ----
        float mx0 = -1e30f, mx1 = -1e30f;
        #pragma unroll
        for (int j = 0; j < 8; j++) {
            mx0 = fmaxf(mx0, fmaxf(sacc[j][0], sacc[j][1]));
            mx1 = fmaxf(mx1, fmaxf(sacc[j][2], sacc[j][3]));
        }
        mx0 = fmaxf(mx0, __shfl_xor_sync(0xffffffffu, mx0, 1));
        mx0 = fmaxf(mx0, __shfl_xor_sync(0xffffffffu, mx0, 2));
        mx1 = fmaxf(mx1, __shfl_xor_sync(0xffffffffu, mx1, 1));
        mx1 = fmaxf(mx1, __shfl_xor_sync(0xffffffffu, mx1, 2));

        const float mn0 = fmaxf(m0, mx0), mn1 = fmaxf(m1, mx1);
        const float e0 = __expf(m0 - mn0), e1 = __expf(m1 - mn1);
        m0 = mn0; m1 = mn1;

        float sum0 = 0.f, sum1 = 0.f;
        #pragma unroll
        for (int j = 0; j < 8; j++) {
            sacc[j][0] = __expf(sacc[j][0] - mn0); sum0 += sacc[j][0];
            sacc[j][1] = __expf(sacc[j][1] - mn0); sum0 += sacc[j][1];
            sacc[j][2] = __expf(sacc[j][2] - mn1); sum1 += sacc[j][2];
            sacc[j][3] = __expf(sacc[j][3] - mn1); sum1 += sacc[j][3];
        }
        sum0 += __shfl_xor_sync(0xffffffffu, sum0, 1);
        sum0 += __shfl_xor_sync(0xffffffffu, sum0, 2);
        sum1 += __shfl_xor_sync(0xffffffffu, sum1, 1);
        sum1 += __shfl_xor_sync(0xffffffffu, sum1, 2);
        l0 = l0 * e0 + sum0;
        l1 = l1 * e1 + sum1;

        #pragma unroll
        for (int j = 0; j < 16; j++) {
            oacc[j][0] *= e0; oacc[j][1] *= e0;
            oacc[j][2] *= e1; oacc[j][3] *= e1;
        }

        // ---- O += P @ V  (P fragments come straight from sacc) ----
        #pragma unroll
        for (int kk = 0; kk < 4; kk++) {
            __half2 ha0 = __floats2half2_rn(sacc[2 * kk][0],     sacc[2 * kk][1]);
            __half2 ha1 = __floats2half2_rn(sacc[2 * kk][2],     sacc[2 * kk][3]);
            __half2 ha2 = __floats2half2_rn(sacc[2 * kk + 1][0], sacc[2 * kk + 1][1]);
            __half2 ha3 = __floats2half2_rn(sacc[2 * kk + 1][2], sacc[2 * kk + 1][3]);
            uint32_t a0 = *(uint32_t*)&ha0;
            uint32_t a1 = *(uint32_t*)&ha1;
            uint32_t a2 = *(uint32_t*)&ha2;
            uint32_t a3 = *(uint32_t*)&ha3;
            #pragma unroll
            for (int v2 = 0; v2 < 8; v2++) {
                uint32_t b0, b1, b2, b3;
                ldm4t(b0, b1, b2, b3, vbase + (uint32_t)(kk * 16 * VS_STRIDE + v2 * 16) * 2);
                mma16816(oacc[2 * v2],     a0, a1, a2, a3, b0, b1);
                mma16816(oacc[2 * v2 + 1], a0, a1, a2, a3, b2, b3);
            }
        }
    }

    // ---- epilogue ----
    const float inv0 = 1.f / l0, inv1 = 1.f / l1;
    const int r0g = t0 + mrow + qr;
    float* op0 = out + (size_t)r0g * (H_HEADS * D_V) + h * D_V + cq;
    float* op1 = op0 + (size_t)8 * (H_HEADS * D_V);
    #pragma unroll
    for (int j = 0; j < 16; j++) {
        *(float2*)(op0 + j * 8) = make_float2(oacc[j][0] * inv0, oacc[j][1] * inv0);
        *(float2*)(op1 + j * 8) = make_float2(oacc[j][2] * inv1, oacc[j][3] * inv1);
    }
}

// ---------------------------------------------------------------------------
extern "C" void kernel_launch(void* const* d_in, const int* in_sizes, int n_in,
                              void* d_out, int out_size)
{
    const float* q    = (const float*)d_in[0];   // (T, H, 192)
    const float* kc   = (const float*)d_in[1];   // (T, 512)
    const float* kpe  = (const float*)d_in[2];   // (T, 64)
    const float* wkvb = (const float*)d_in[3];   // (512, 4096)
    const float* wuv  = (const float*)d_in[4];   // (16, 512, 128)
    float* out = (float*)d_out;                  // (T, 2048)

    cudaFuncSetAttribute(attn_kernel,
                         cudaFuncAttributeMaxDynamicSharedMemorySize, ATTN_SMEM);

    prep_gemm<<<dim3(T_SEQ / 64, 2048 / 64, 2), 256>>>(kc, wkvb, wuv);
    rope_fill<<<(H_HEADS * T_SEQ * D_ROPE + 255) / 256, 256>>>(kpe);
    q_convert<<<(T_SEQ * H_HEADS * D_QK / 4 + 255) / 256, 256>>>(q);
    attn_kernel<<<dim3(T_SEQ / 64, H_HEADS), 128, ATTN_SMEM>>>(out);
}

// round 3
// speedup vs baseline: 11.4243x; 2.2546x over previous
#include <cuda_runtime.h>
#include <cuda_fp16.h>
#include <stdint.h>

#define T_SEQ 2048
#define H_HEADS 16
#define D_QK 192      // NOPE + ROPE
#define D_NOPE 128
#define D_ROPE 64
#define D_V 128
#define L_LORA 512
#define SCALE_F 0.07216878364870323f   // 1/sqrt(192)
#define LOG2E   1.4426950408889634f

// fp16 staging (device globals: allocation-free rule)
__device__ __half g_Qh[T_SEQ * H_HEADS * D_QK];   // [t][h][192], pre-scaled by SCALE*LOG2E
__device__ __half g_Kh[H_HEADS * T_SEQ * D_QK];   // [h][t][192]
__device__ __half g_Vh[H_HEADS * T_SEQ * D_V];    // [h][t][128]
__device__ __half g_kch[T_SEQ * L_LORA];          // fp16 k_c
__device__ __half g_Bh[L_LORA * 4096];            // [l][n]: n<2048 K-cols, else V-cols

// ---------------------------------------------------------------------------
// PTX helpers
// ---------------------------------------------------------------------------
__device__ __forceinline__ uint32_t sptr(const void* p) {
    return (uint32_t)__cvta_generic_to_shared(p);
}
__device__ __forceinline__ void ldm4(uint32_t& r0, uint32_t& r1, uint32_t& r2, uint32_t& r3, uint32_t addr) {
    asm volatile("ldmatrix.sync.aligned.m8n8.x4.shared.b16 {%0,%1,%2,%3}, [%4];"
                 : "=r"(r0), "=r"(r1), "=r"(r2), "=r"(r3) : "r"(addr));
}
__device__ __forceinline__ void ldm4t(uint32_t& r0, uint32_t& r1, uint32_t& r2, uint32_t& r3, uint32_t addr) {
    asm volatile("ldmatrix.sync.aligned.m8n8.x4.trans.shared.b16 {%0,%1,%2,%3}, [%4];"
                 : "=r"(r0), "=r"(r1), "=r"(r2), "=r"(r3) : "r"(addr));
}
__device__ __forceinline__ void mma16816(float* c,
                                         uint32_t a0, uint32_t a1, uint32_t a2, uint32_t a3,
                                         uint32_t b0, uint32_t b1) {
    asm volatile("mma.sync.aligned.m16n8k16.row.col.f32.f16.f16.f32 "
                 "{%0,%1,%2,%3}, {%4,%5,%6,%7}, {%8,%9}, {%0,%1,%2,%3};"
                 : "+f"(c[0]), "+f"(c[1]), "+f"(c[2]), "+f"(c[3])
                 : "r"(a0), "r"(a1), "r"(a2), "r"(a3), "r"(b0), "r"(b1));
}
__device__ __forceinline__ void cpa16(void* s, const void* g) {
    asm volatile("cp.async.cg.shared.global [%0], [%1], 16;" :: "r"(sptr(s)), "l"(g));
}
#define CP_COMMIT asm volatile("cp.async.commit_group;")
#define CP_WAIT1  asm volatile("cp.async.wait_group 1;")
__device__ __forceinline__ float ex2(float x) {
    float y; asm("ex2.approx.f32 %0, %1;" : "=f"(y) : "f"(x)); return y;
}

// ---------------------------------------------------------------------------
// Conversions
// ---------------------------------------------------------------------------
__global__ __launch_bounds__(256) void kc_convert(const float* __restrict__ kc)
{
    int i = blockIdx.x * blockDim.x + threadIdx.x;
    if (i >= T_SEQ * L_LORA / 4) return;
    float4 v = ((const float4*)kc)[i];
    ((__half2*)g_kch)[2 * i]     = __floats2half2_rn(v.x, v.y);
    ((__half2*)g_kch)[2 * i + 1] = __floats2half2_rn(v.z, v.w);
}

__global__ __launch_bounds__(256) void b_convert(
    const float* __restrict__ wkvb, const float* __restrict__ wuv)
{
    int idx = blockIdx.x * blockDim.x + threadIdx.x;
    if (idx >= L_LORA * 4096) return;
    int l = idx >> 12;
    int n = idx & 4095;
    float v;
    if (n < 2048) {
        int h = n >> 7, d = n & 127;
        v = wkvb[(size_t)l * 4096 + h * 256 + d];
    } else {
        int n2 = n - 2048;
        int h = n2 >> 7, d = n2 & 127;
        v = wuv[((size_t)h * 512 + l) * 128 + d];
    }
    g_Bh[idx] = __float2half(v);
}

__global__ __launch_bounds__(256) void q_convert(const float* __restrict__ q)
{
    int i = blockIdx.x * blockDim.x + threadIdx.x;
    const int n4 = (T_SEQ * H_HEADS * D_QK) / 4;
    if (i >= n4) return;
    const float s = SCALE_F * LOG2E;
    float4 v = ((const float4*)q)[i];
    ((__half2*)g_Qh)[2 * i]     = __floats2half2_rn(v.x * s, v.y * s);
    ((__half2*)g_Qh)[2 * i + 1] = __floats2half2_rn(v.z * s, v.w * s);
}

__global__ __launch_bounds__(256) void rope_fill(const float* __restrict__ kpe)
{
    int idx = blockIdx.x * blockDim.x + threadIdx.x;
    if (idx >= H_HEADS * T_SEQ * D_ROPE) return;
    int r = idx & 63;
    int t = (idx >> 6) & (T_SEQ - 1);
    int h = idx >> 17;
    g_Kh[((size_t)h * T_SEQ + t) * D_QK + D_NOPE + r] = __float2half(kpe[t * D_ROPE + r]);
}

// ---------------------------------------------------------------------------
// prep_mma: C[2048 x 4096] = g_kch[2048 x 512] @ g_Bh[512 x 4096] (fp16, fp32 acc)
// CTA tile 128x128, k-chunk 32, 8 warps (2x4), warp tile 64x32, cp.async 2-stage.
// ---------------------------------------------------------------------------
#define AS_STRIDE 40
#define BS_STRIDE 136

__global__ __launch_bounds__(256) void prep_mma()
{
    __shared__ __half As[2][128 * AS_STRIDE];
    __shared__ __half Bs[2][32 * BS_STRIDE];

    const int t0 = blockIdx.x * 128;
    const int n0 = blockIdx.y * 128;
    const int tid = threadIdx.x;
    const int warp = tid >> 5;
    const int lane = tid & 31;
    const int mw = (warp >> 2) * 64;
    const int nw = (warp & 3) * 32;

    auto load_chunk = [&](int l0, int b) {
        #pragma unroll
        for (int i = tid; i < 512; i += 256) {          // A: 128 rows x 4 segs
            int r = i >> 2, s = i & 3;
            cpa16(&As[b][r * AS_STRIDE + s * 8],
                  g_kch + (size_t)(t0 + r) * L_LORA + l0 + s * 8);
        }
        #pragma unroll
        for (int i = tid; i < 512; i += 256) {          // B: 32 rows x 16 segs
            int r = i >> 4, s = i & 15;
            cpa16(&Bs[b][r * BS_STRIDE + s * 8],
                  g_Bh + (size_t)(l0 + r) * 4096 + n0 + s * 8);
        }
    };

    load_chunk(0, 0);  CP_COMMIT;
    load_chunk(32, 1); CP_COMMIT;

    float acc[4][4][4];
    #pragma unroll
    for (int mt = 0; mt < 4; mt++)
        #pragma unroll
        for (int nt = 0; nt < 4; nt++)
            #pragma unroll
            for (int e = 0; e < 4; e++) acc[mt][nt][e] = 0.f;

    const uint32_t aoff = ((mw + (lane & 15)) * AS_STRIDE + ((lane >> 4) << 3)) * 2;
    const uint32_t boff = ((lane & 15) * BS_STRIDE + nw + ((lane >> 4) << 3)) * 2;
    const uint32_t abase[2] = { sptr(As[0]) + aoff, sptr(As[1]) + aoff };
    const uint32_t bbase[2] = { sptr(Bs[0]) + boff, sptr(Bs[1]) + boff };

    for (int c = 0; c < 16; c++) {
        const int b = c & 1;
        CP_WAIT1;
        __syncthreads();

        #pragma unroll
        for (int ks = 0; ks < 2; ks++) {
            uint32_t a[4][4];
            #pragma unroll
            for (int mt = 0; mt < 4; mt++)
                ldm4(a[mt][0], a[mt][1], a[mt][2], a[mt][3],
                     abase[b] + (uint32_t)(mt * 16 * AS_STRIDE + ks * 16) * 2);
            #pragma unroll
            for (int j2 = 0; j2 < 2; j2++) {
                uint32_t b0, b1, b2, b3;
                ldm4t(b0, b1, b2, b3,
                      bbase[b] + (uint32_t)(ks * 16 * BS_STRIDE + j2 * 16) * 2);
                #pragma unroll
                for (int mt = 0; mt < 4; mt++) {
                    mma16816(acc[mt][2 * j2],     a[mt][0], a[mt][1], a[mt][2], a[mt][3], b0, b1);
                    mma16816(acc[mt][2 * j2 + 1], a[mt][0], a[mt][1], a[mt][2], a[mt][3], b2, b3);
                }
            }
        }

        __syncthreads();
        if (c + 2 < 16) load_chunk((c + 2) * 32, b);
        CP_COMMIT;
    }

    // epilogue
    const int qr = lane >> 2;
    const int cq = (lane & 3) * 2;
    #pragma unroll
    for (int mt = 0; mt < 4; mt++) {
        #pragma unroll
        for (int nt = 0; nt < 4; nt++) {
            const int row = t0 + mw + mt * 16 + qr;
            const int col = n0 + nw + nt * 8 + cq;
            __half* dst;
            if (col < 2048) {
                int h = col >> 7, d = col & 127;
                dst = g_Kh + ((size_t)h * T_SEQ) * D_QK + d;
                *(__half2*)(dst + (size_t)row * D_QK)       = __floats2half2_rn(acc[mt][nt][0], acc[mt][nt][1]);
                *(__half2*)(dst + (size_t)(row + 8) * D_QK) = __floats2half2_rn(acc[mt][nt][2], acc[mt][nt][3]);
            } else {
                int c2 = col - 2048;
                int h = c2 >> 7, d = c2 & 127;
                dst = g_Vh + ((size_t)h * T_SEQ) * D_V + d;
                *(__half2*)(dst + (size_t)row * D_V)       = __floats2half2_rn(acc[mt][nt][0], acc[mt][nt][1]);
                *(__half2*)(dst + (size_t)(row + 8) * D_V) = __floats2half2_rn(acc[mt][nt][2], acc[mt][nt][3]);
            }
        }
    }
}

// ---------------------------------------------------------------------------
// Flash attention: Q frags in regs, cp.async double-buffered K/V, ex2 softmax.
// Block = 64 q rows, 4 warps x 16 rows; key tiles of 64. Grid reversed.
// ---------------------------------------------------------------------------
#define KS_STRIDE 200
#define VS_STRIDE 136
#define KBUF (64 * KS_STRIDE)
#define VBUF (64 * VS_STRIDE)
#define ATTN_SMEM ((2 * KBUF + 2 * VBUF) * 2)

__global__ __launch_bounds__(128, 2) void attn_kernel(float* __restrict__ out)
{
    extern __shared__ __half sm[];
    __half* Ks0 = sm;
    __half* Ks1 = Ks0 + KBUF;
    __half* Vs0 = Ks1 + KBUF;
    __half* Vs1 = Vs0 + VBUF;

    const int h  = blockIdx.y;
    const int bx = gridDim.x - 1 - blockIdx.x;    // heavy blocks launch first
    const int t0 = bx * 64;
    const int nt = bx + 1;
    const int tid  = threadIdx.x;
    const int warp = tid >> 5;
    const int lane = tid & 31;
    const int mrow = warp * 16;
    const int qr = lane >> 2;
    const int cq = (lane & 3) * 2;

    // ---- stage Q through Ks0, pull fragments into registers ----
    for (int i = tid; i < 64 * 24; i += 128) {
        int r = i / 24, c = i - r * 24;
        *(uint4*)(Ks0 + r * KS_STRIDE + c * 8) =
            *(const uint4*)(g_Qh + ((size_t)(t0 + r) * H_HEADS + h) * D_QK + c * 8);
    }
    __syncthreads();
    uint32_t qf[12][4];
    {
        const uint32_t qbase = sptr(Ks0 + (mrow + (lane & 15)) * KS_STRIDE + ((lane >> 4) << 3));
        #pragma unroll
        for (int kk = 0; kk < 12; kk++)
            ldm4(qf[kk][0], qf[kk][1], qf[kk][2], qf[kk][3], qbase + kk * 32);
    }
    __syncthreads();

    const uint32_t koff = (((lane & 7) + ((lane >> 4) << 3)) * KS_STRIDE + (((lane >> 3) & 1) << 3)) * 2;
    const uint32_t voff = ((lane & 15) * VS_STRIDE + ((lane >> 4) << 3)) * 2;
    const uint32_t kb[2] = { sptr(Ks0) + koff, sptr(Ks1) + koff };
    const uint32_t vb[2] = { sptr(Vs0) + voff, sptr(Vs1) + voff };

    auto load_tile = [&](int tile, int b) {
        __half* kd = b ? Ks1 : Ks0;
        __half* vd = b ? Vs1 : Vs0;
        const int s0 = tile * 64;
        #pragma unroll
        for (int i = tid; i < 64 * 24; i += 128) {
            int r = i / 24, c = i - r * 24;
            cpa16(kd + r * KS_STRIDE + c * 8,
                  g_Kh + ((size_t)h * T_SEQ + s0 + r) * D_QK + c * 8);
        }
        #pragma unroll
        for (int i = tid; i < 64 * 16; i += 128) {
            int r = i >> 4, c = i & 15;
            cpa16(vd + r * VS_STRIDE + c * 8,
                  g_Vh + ((size_t)h * T_SEQ + s0 + r) * D_V + c * 8);
        }
    };

    load_tile(0, 0); CP_COMMIT;
    if (nt > 1) load_tile(1, 1);
    CP_COMMIT;

    float m0 = -1e30f, m1 = -1e30f, l0 = 0.f, l1 = 0.f;
    float oacc[16][4];
    #pragma unroll
    for (int j = 0; j < 16; j++)
        #pragma unroll
        for (int e = 0; e < 4; e++) oacc[j][e] = 0.f;

    for (int tile = 0; tile < nt; tile++) {
        const int b = tile & 1;
        CP_WAIT1;
        __syncthreads();

        // ---- scores S = Q @ K^T ----
        float sacc[8][4];
        #pragma unroll
        for (int j = 0; j < 8; j++)
            #pragma unroll
            for (int e = 0; e < 4; e++) sacc[j][e] = 0.f;

        #pragma unroll
        for (int kk = 0; kk < 12; kk++) {
            #pragma unroll
            for (int j2 = 0; j2 < 4; j2++) {
                uint32_t b0, b1, b2, b3;
                ldm4(b0, b1, b2, b3, kb[b] + (uint32_t)(j2 * 16 * KS_STRIDE + kk * 16) * 2);
                mma16816(sacc[2 * j2],     qf[kk][0], qf[kk][1], qf[kk][2], qf[kk][3], b0, b1);
                mma16816(sacc[2 * j2 + 1], qf[kk][0], qf[kk][1], qf[kk][2], qf[kk][3], b2, b3);
            }
        }

        // ---- causal mask (diagonal tile only) ----
        if (tile == bx) {
            const int row0 = mrow + qr;
            #pragma unroll
            for (int j = 0; j < 8; j++) {
                int c0 = j * 8 + cq;
                if (c0     > row0)     sacc[j][0] = -1e30f;
                if (c0 + 1 > row0)     sacc[j][1] = -1e30f;
                if (c0     > row0 + 8) sacc[j][2] = -1e30f;
                if (c0 + 1 > row0 + 8) sacc[j][3] = -1e30f;
            }
        }

        // ---- online softmax (log2 domain) ----
        float mx0 = -1e30f, mx1 = -1e30f;
        #pragma unroll
        for (int j = 0; j < 8; j++) {
            mx0 = fmaxf(mx0, fmaxf(sacc[j][0], sacc[j][1]));
            mx1 = fmaxf(mx1, fmaxf(sacc[j][2], sacc[j][3]));
        }
        mx0 = fmaxf(mx0, __shfl_xor_sync(0xffffffffu, mx0, 1));
        mx0 = fmaxf(mx0, __shfl_xor_sync(0xffffffffu, mx0, 2));
        mx1 = fmaxf(mx1, __shfl_xor_sync(0xffffffffu, mx1, 1));
        mx1 = fmaxf(mx1, __shfl_xor_sync(0xffffffffu, mx1, 2));

        const float mn0 = fmaxf(m0, mx0), mn1 = fmaxf(m1, mx1);
        const float e0 = ex2(m0 - mn0), e1 = ex2(m1 - mn1);
        m0 = mn0; m1 = mn1;

        float sum0 = 0.f, sum1 = 0.f;
        #pragma unroll
        for (int j = 0; j < 8; j++) {
            sacc[j][0] = ex2(sacc[j][0] - mn0); sum0 += sacc[j][0];
            sacc[j][1] = ex2(sacc[j][1] - mn0); sum0 += sacc[j][1];
            sacc[j][2] = ex2(sacc[j][2] - mn1); sum1 += sacc[j][2];
            sacc[j][3] = ex2(sacc[j][3] - mn1); sum1 += sacc[j][3];
        }
        sum0 += __shfl_xor_sync(0xffffffffu, sum0, 1);
        sum0 += __shfl_xor_sync(0xffffffffu, sum0, 2);
        sum1 += __shfl_xor_sync(0xffffffffu, sum1, 1);
        sum1 += __shfl_xor_sync(0xffffffffu, sum1, 2);
        l0 = l0 * e0 + sum0;
        l1 = l1 * e1 + sum1;

        #pragma unroll
        for (int j = 0; j < 16; j++) {
            oacc[j][0] *= e0; oacc[j][1] *= e0;
            oacc[j][2] *= e1; oacc[j][3] *= e1;
        }

        // ---- O += P @ V ----
        #pragma unroll
        for (int kk = 0; kk < 4; kk++) {
            __half2 ha0 = __floats2half2_rn(sacc[2 * kk][0],     sacc[2 * kk][1]);
            __half2 ha1 = __floats2half2_rn(sacc[2 * kk][2],     sacc[2 * kk][3]);
            __half2 ha2 = __floats2half2_rn(sacc[2 * kk + 1][0], sacc[2 * kk + 1][1]);
            __half2 ha3 = __floats2half2_rn(sacc[2 * kk + 1][2], sacc[2 * kk + 1][3]);
            uint32_t a0 = *(uint32_t*)&ha0;
            uint32_t a1 = *(uint32_t*)&ha1;
            uint32_t a2 = *(uint32_t*)&ha2;
            uint32_t a3 = *(uint32_t*)&ha3;
            #pragma unroll
            for (int v2 = 0; v2 < 8; v2++) {
                uint32_t b0, b1, b2, b3;
                ldm4t(b0, b1, b2, b3, vb[b] + (uint32_t)(kk * 16 * VS_STRIDE + v2 * 16) * 2);
                mma16816(oacc[2 * v2],     a0, a1, a2, a3, b0, b1);
                mma16816(oacc[2 * v2 + 1], a0, a1, a2, a3, b2, b3);
            }
        }

        __syncthreads();
        if (tile + 2 < nt) load_tile(tile + 2, b);
        CP_COMMIT;
    }

    // ---- epilogue ----
    const float inv0 = 1.f / l0, inv1 = 1.f / l1;
    const int r0g = t0 + mrow + qr;
    float* op0 = out + (size_t)r0g * (H_HEADS * D_V) + h * D_V + cq;
    float* op1 = op0 + (size_t)8 * (H_HEADS * D_V);
    #pragma unroll
    for (int j = 0; j < 16; j++) {
        *(float2*)(op0 + j * 8) = make_float2(oacc[j][0] * inv0, oacc[j][1] * inv0);
        *(float2*)(op1 + j * 8) = make_float2(oacc[j][2] * inv1, oacc[j][3] * inv1);
    }
}

// ---------------------------------------------------------------------------
extern "C" void kernel_launch(void* const* d_in, const int* in_sizes, int n_in,
                              void* d_out, int out_size)
{
    const float* q    = (const float*)d_in[0];   // (T, H, 192)
    const float* kc   = (const float*)d_in[1];   // (T, 512)
    const float* kpe  = (const float*)d_in[2];   // (T, 64)
    const float* wkvb = (const float*)d_in[3];   // (512, 4096)
    const float* wuv  = (const float*)d_in[4];   // (16, 512, 128)
    float* out = (float*)d_out;                  // (T, 2048)

    cudaFuncSetAttribute(attn_kernel,
                         cudaFuncAttributeMaxDynamicSharedMemorySize, ATTN_SMEM);

    kc_convert<<<(T_SEQ * L_LORA / 4 + 255) / 256, 256>>>(kc);
    b_convert<<<(L_LORA * 4096 + 255) / 256, 256>>>(wkvb, wuv);
    q_convert<<<(T_SEQ * H_HEADS * D_QK / 4 + 255) / 256, 256>>>(q);
    rope_fill<<<(H_HEADS * T_SEQ * D_ROPE + 255) / 256, 256>>>(kpe);
    prep_mma<<<dim3(T_SEQ / 128, 4096 / 128), 256>>>();
    attn_kernel<<<dim3(T_SEQ / 64, H_HEADS), 128, ATTN_SMEM>>>(out);
}